// round 1
// baseline (speedup 1.0000x reference)
#include <cuda_runtime.h>
#include <math.h>

// Problem constants
#define Bz 8
#define Sz 1024
#define Dz 512
#define Hz 8
#define DHz 64
#define FFz 2048
#define Lz 4
#define Nz (Bz*Sz)          // 8192 rows

// Scratch layout (floats) in one big device-global array
static constexpr size_t XBUF  = 0;
static constexpr size_t QBUF  = XBUF + (size_t)Nz*Dz;
static constexpr size_t KBUF  = QBUF + (size_t)Nz*Dz;
static constexpr size_t VBUF  = KBUF + (size_t)Nz*Dz;
static constexpr size_t ABUF  = VBUF + (size_t)Nz*Dz;
static constexpr size_t TBUF  = ABUF + (size_t)Nz*Dz;
static constexpr size_t YBUF  = TBUF + (size_t)Nz*Dz;
static constexpr size_t FBUF  = YBUF + (size_t)Nz*Dz;
static constexpr size_t SCBUF = FBUF + (size_t)Nz*FFz;
static constexpr size_t SCRATCH_TOTAL = SCBUF + (size_t)Bz*Hz*Sz*Sz;

__device__ float g_scratch[SCRATCH_TOTAL];

// ---------------------------------------------------------------------------
// Positional encoding: out = x + pe(s, d)
// ---------------------------------------------------------------------------
__global__ __launch_bounds__(256) void posenc_kernel(const float* __restrict__ x,
                                                     float* __restrict__ out) {
    int idx = blockIdx.x * 256 + threadIdx.x;      // over Nz*Dz
    int d = idx & (Dz - 1);
    int s = (idx >> 9) & (Sz - 1);
    int i2 = d & ~1;
    // div = exp(-(ln 10000 / D) * i2), computed in double then rounded
    float divv = (float)exp((double)i2 * (-9.210340371976184 / (double)Dz));
    float ang = (float)s * divv;
    float pe = (d & 1) ? cosf(ang) : sinf(ang);
    out[idx] = x[idx] + pe;
}

// ---------------------------------------------------------------------------
// GEMM: C[N,M] = A[N,K] @ W[K,M] + bias, optional ReLU
// BM=BN=128, BK=16, 256 threads, 8x8 per thread. Dims divisible (N=8192,
// K,M in {512,2048}).
// ---------------------------------------------------------------------------
template<bool RELU>
__global__ __launch_bounds__(256) void gemm_bias_kernel(
    const float* __restrict__ A, const float* __restrict__ W,
    const float* __restrict__ bias, float* __restrict__ C,
    int K, int M)
{
    __shared__ float As[16][128];   // [k][m]
    __shared__ float Ws[16][128];   // [k][n]
    int tid = threadIdx.x;
    int tx = tid & 15, ty = tid >> 4;
    int row0 = blockIdx.y * 128;
    int col0 = blockIdx.x * 128;
    float acc[8][8];
    #pragma unroll
    for (int i = 0; i < 8; i++)
        #pragma unroll
        for (int j = 0; j < 8; j++) acc[i][j] = 0.f;

    int ar  = tid >> 2;           // 0..63 (+64)
    int akc = (tid & 3) << 2;     // 0,4,8,12
    int wr  = tid >> 5;           // 0..7 (+8)
    int wc  = (tid & 31) << 2;    // 0..124

    for (int k0 = 0; k0 < K; k0 += 16) {
        #pragma unroll
        for (int i = 0; i < 2; i++) {
            int r = ar + i * 64;
            float4 av = *(const float4*)&A[(size_t)(row0 + r) * K + k0 + akc];
            As[akc + 0][r] = av.x; As[akc + 1][r] = av.y;
            As[akc + 2][r] = av.z; As[akc + 3][r] = av.w;
            int rw = wr + i * 8;
            float4 wv = *(const float4*)&W[(size_t)(k0 + rw) * M + col0 + wc];
            *(float4*)&Ws[rw][wc] = wv;
        }
        __syncthreads();
        #pragma unroll
        for (int kk = 0; kk < 16; kk++) {
            float ra[8], rb[8];
            *(float4*)&ra[0] = *(const float4*)&As[kk][ty * 8];
            *(float4*)&ra[4] = *(const float4*)&As[kk][ty * 8 + 4];
            *(float4*)&rb[0] = *(const float4*)&Ws[kk][tx * 8];
            *(float4*)&rb[4] = *(const float4*)&Ws[kk][tx * 8 + 4];
            #pragma unroll
            for (int i = 0; i < 8; i++)
                #pragma unroll
                for (int j = 0; j < 8; j++) acc[i][j] += ra[i] * rb[j];
        }
        __syncthreads();
    }

    float bb[8];
    *(float4*)&bb[0] = *(const float4*)&bias[col0 + tx * 8];
    *(float4*)&bb[4] = *(const float4*)&bias[col0 + tx * 8 + 4];
    #pragma unroll
    for (int i = 0; i < 8; i++) {
        int r = row0 + ty * 8 + i;
        float o[8];
        #pragma unroll
        for (int j = 0; j < 8; j++) {
            float v = acc[i][j] + bb[j];
            if (RELU) v = fmaxf(v, 0.f);
            o[j] = v;
        }
        *(float4*)&C[(size_t)r * M + col0 + tx * 8]     = *(float4*)&o[0];
        *(float4*)&C[(size_t)r * M + col0 + tx * 8 + 4] = *(float4*)&o[4];
    }
}

// ---------------------------------------------------------------------------
// QK^T: Sc[bh, q, k] = (1/8) * sum_d Q[b,q,h*64+d] * K[b,k,h*64+d]
// 128x128 tile per block, d-loop BK=16 (4 iters), 8x8 per thread
// ---------------------------------------------------------------------------
__global__ __launch_bounds__(256) void qk_kernel(
    const float* __restrict__ Q, const float* __restrict__ Kmat,
    float* __restrict__ Sc)
{
    __shared__ float Qs[16][128];   // [d][q]
    __shared__ float Ks[16][128];   // [d][k]
    int tid = threadIdx.x;
    int tx = tid & 15, ty = tid >> 4;
    int bh = blockIdx.z;
    int b = bh >> 3, h = bh & 7;
    int q0 = blockIdx.y * 128;
    int k0c = blockIdx.x * 128;
    const float* Qb = Q    + ((size_t)b * Sz + q0)  * Dz + h * DHz;
    const float* Kb = Kmat + ((size_t)b * Sz + k0c) * Dz + h * DHz;

    float acc[8][8];
    #pragma unroll
    for (int i = 0; i < 8; i++)
        #pragma unroll
        for (int j = 0; j < 8; j++) acc[i][j] = 0.f;

    int ar  = tid >> 2;
    int akc = (tid & 3) << 2;

    for (int d0 = 0; d0 < DHz; d0 += 16) {
        #pragma unroll
        for (int i = 0; i < 2; i++) {
            int r = ar + i * 64;
            float4 qv = *(const float4*)&Qb[(size_t)r * Dz + d0 + akc];
            Qs[akc + 0][r] = qv.x; Qs[akc + 1][r] = qv.y;
            Qs[akc + 2][r] = qv.z; Qs[akc + 3][r] = qv.w;
            float4 kv = *(const float4*)&Kb[(size_t)r * Dz + d0 + akc];
            Ks[akc + 0][r] = kv.x; Ks[akc + 1][r] = kv.y;
            Ks[akc + 2][r] = kv.z; Ks[akc + 3][r] = kv.w;
        }
        __syncthreads();
        #pragma unroll
        for (int kk = 0; kk < 16; kk++) {
            float ra[8], rb[8];
            *(float4*)&ra[0] = *(const float4*)&Qs[kk][ty * 8];
            *(float4*)&ra[4] = *(const float4*)&Qs[kk][ty * 8 + 4];
            *(float4*)&rb[0] = *(const float4*)&Ks[kk][tx * 8];
            *(float4*)&rb[4] = *(const float4*)&Ks[kk][tx * 8 + 4];
            #pragma unroll
            for (int i = 0; i < 8; i++)
                #pragma unroll
                for (int j = 0; j < 8; j++) acc[i][j] += ra[i] * rb[j];
        }
        __syncthreads();
    }

    #pragma unroll
    for (int i = 0; i < 8; i++) {
        float* out = Sc + ((size_t)bh * Sz + q0 + ty * 8 + i) * Sz + k0c + tx * 8;
        float o[8];
        #pragma unroll
        for (int j = 0; j < 8; j++) o[j] = acc[i][j] * 0.125f;
        *(float4*)&out[0] = *(float4*)&o[0];
        *(float4*)&out[4] = *(float4*)&o[4];
    }
}

// ---------------------------------------------------------------------------
// Masked softmax over rows of the score matrix. One block per (b,h,q) row.
// ---------------------------------------------------------------------------
__global__ __launch_bounds__(256) void softmax_kernel(float* __restrict__ Sc,
                                                      const int* __restrict__ lens)
{
    int row = blockIdx.x;                 // 0 .. B*H*S-1
    int b = row >> 13;                    // row / (H*S)
    int len = lens[b];
    float* p = Sc + (size_t)row * Sz;
    int tid = threadIdx.x;
    int lane = tid & 31, w = tid >> 5;
    __shared__ float sh[8];

    float v[4];
    float mx = -1e30f;
    #pragma unroll
    for (int i = 0; i < 4; i++) {
        int k = tid + (i << 8);
        v[i] = p[k];
        if (k < len && v[i] > mx) mx = v[i];
    }
    #pragma unroll
    for (int o = 16; o; o >>= 1) mx = fmaxf(mx, __shfl_xor_sync(0xffffffffu, mx, o));
    if (lane == 0) sh[w] = mx;
    __syncthreads();
    mx = sh[0];
    #pragma unroll
    for (int i = 1; i < 8; i++) mx = fmaxf(mx, sh[i]);
    __syncthreads();

    float sum = 0.f;
    #pragma unroll
    for (int i = 0; i < 4; i++) {
        int k = tid + (i << 8);
        float e = (k < len) ? __expf(v[i] - mx) : 0.f;
        v[i] = e;
        sum += e;
    }
    #pragma unroll
    for (int o = 16; o; o >>= 1) sum += __shfl_xor_sync(0xffffffffu, sum, o);
    if (lane == 0) sh[w] = sum;
    __syncthreads();
    float tot = 0.f;
    #pragma unroll
    for (int i = 0; i < 8; i++) tot += sh[i];
    float inv = 1.0f / tot;
    #pragma unroll
    for (int i = 0; i < 4; i++) p[tid + (i << 8)] = v[i] * inv;
}

// ---------------------------------------------------------------------------
// P @ V: O[b,q,h*64+c] = sum_k P[bh,q,k] * V[b,k,h*64+c]
// BM=128 (q), BN=64 (=DH), BK=16, 128 threads, 8x8 per thread
// ---------------------------------------------------------------------------
__global__ __launch_bounds__(128) void pv_kernel(
    const float* __restrict__ P, const float* __restrict__ V,
    float* __restrict__ O)
{
    __shared__ float Ps[16][128];   // [k][q]
    __shared__ float Vs[16][64];    // [k][dh]
    int tid = threadIdx.x;          // 0..127
    int tx = tid & 7, ty = tid >> 3;   // tx 0..7 (cols), ty 0..15 (rows)
    int bh = blockIdx.y;
    int b = bh >> 3, h = bh & 7;
    int q0 = blockIdx.x * 128;
    const float* Pb = P + ((size_t)bh * Sz + q0) * Sz;
    const float* Vb = V + (size_t)b * Sz * Dz + h * DHz;

    float acc[8][8];
    #pragma unroll
    for (int i = 0; i < 8; i++)
        #pragma unroll
        for (int j = 0; j < 8; j++) acc[i][j] = 0.f;

    for (int k0 = 0; k0 < Sz; k0 += 16) {
        #pragma unroll
        for (int i = 0; i < 4; i++) {
            int e = tid + i * 128;         // 0..511 float4 units
            int r = e >> 2;                // q row 0..127
            int kc = (e & 3) << 2;         // k 0,4,8,12
            float4 pv4 = *(const float4*)&Pb[(size_t)r * Sz + k0 + kc];
            Ps[kc + 0][r] = pv4.x; Ps[kc + 1][r] = pv4.y;
            Ps[kc + 2][r] = pv4.z; Ps[kc + 3][r] = pv4.w;
        }
        #pragma unroll
        for (int i = 0; i < 2; i++) {
            int e = tid + i * 128;         // 0..255 float4 units
            int vr = e >> 4;               // k row 0..15
            int vc = (e & 15) << 2;        // dh col 0..60
            float4 vv = *(const float4*)&Vb[(size_t)(k0 + vr) * Dz + vc];
            *(float4*)&Vs[vr][vc] = vv;
        }
        __syncthreads();
        #pragma unroll
        for (int kk = 0; kk < 16; kk++) {
            float ra[8], rb[8];
            *(float4*)&ra[0] = *(const float4*)&Ps[kk][ty * 8];
            *(float4*)&ra[4] = *(const float4*)&Ps[kk][ty * 8 + 4];
            *(float4*)&rb[0] = *(const float4*)&Vs[kk][tx * 8];
            *(float4*)&rb[4] = *(const float4*)&Vs[kk][tx * 8 + 4];
            #pragma unroll
            for (int i = 0; i < 8; i++)
                #pragma unroll
                for (int j = 0; j < 8; j++) acc[i][j] += ra[i] * rb[j];
        }
        __syncthreads();
    }

    #pragma unroll
    for (int i = 0; i < 8; i++) {
        float* out = O + ((size_t)b * Sz + q0 + ty * 8 + i) * Dz + h * DHz + tx * 8;
        *(float4*)&out[0] = *(float4*)&acc[i][0];
        *(float4*)&out[4] = *(float4*)&acc[i][4];
    }
}

// ---------------------------------------------------------------------------
// LayerNorm: out = g * (s - mean)/(sqrt(var_unbiased) + eps) + be,  s = Xa+Xb
// One block (256 threads) per row of D=512.
// ---------------------------------------------------------------------------
__global__ __launch_bounds__(256) void ln_kernel(
    const float* __restrict__ Xa, const float* __restrict__ Xb,
    const float* __restrict__ g, const float* __restrict__ be,
    float* __restrict__ out)
{
    int n = blockIdx.x;
    const float* a = Xa + (size_t)n * Dz;
    const float* c = Xb + (size_t)n * Dz;
    int tid = threadIdx.x;
    int lane = tid & 31, w = tid >> 5;
    __shared__ float sh[8];

    float s0 = a[tid] + c[tid];
    float s1 = a[tid + 256] + c[tid + 256];

    float sum = s0 + s1;
    #pragma unroll
    for (int o = 16; o; o >>= 1) sum += __shfl_xor_sync(0xffffffffu, sum, o);
    if (lane == 0) sh[w] = sum;
    __syncthreads();
    float tot = 0.f;
    #pragma unroll
    for (int i = 0; i < 8; i++) tot += sh[i];
    __syncthreads();
    float mean = tot * (1.0f / (float)Dz);

    float d0 = s0 - mean, d1 = s1 - mean;
    float ss = d0 * d0 + d1 * d1;
    #pragma unroll
    for (int o = 16; o; o >>= 1) ss += __shfl_xor_sync(0xffffffffu, ss, o);
    if (lane == 0) sh[w] = ss;
    __syncthreads();
    float tot2 = 0.f;
    #pragma unroll
    for (int i = 0; i < 8; i++) tot2 += sh[i];
    float var = tot2 * (1.0f / (float)(Dz - 1));
    float r = 1.0f / (sqrtf(var) + 1e-6f);

    out[(size_t)n * Dz + tid]       = g[tid]       * d0 * r + be[tid];
    out[(size_t)n * Dz + tid + 256] = g[tid + 256] * d1 * r + be[tid + 256];
}

// ---------------------------------------------------------------------------
// Host orchestration
// ---------------------------------------------------------------------------
extern "C" void kernel_launch(void* const* d_in, const int* in_sizes, int n_in,
                              void* d_out, int out_size)
{
    const float* x    = (const float*)d_in[0];
    const int*   lens = (const int*)  d_in[1];
    const float* Wq   = (const float*)d_in[2];
    const float* bq   = (const float*)d_in[3];
    const float* Wk   = (const float*)d_in[4];
    const float* bk   = (const float*)d_in[5];
    const float* Wv   = (const float*)d_in[6];
    const float* bv   = (const float*)d_in[7];
    const float* Wo   = (const float*)d_in[8];
    const float* bo   = (const float*)d_in[9];
    const float* W1   = (const float*)d_in[10];
    const float* b1   = (const float*)d_in[11];
    const float* W2   = (const float*)d_in[12];
    const float* b2   = (const float*)d_in[13];
    const float* g1   = (const float*)d_in[14];
    const float* be1  = (const float*)d_in[15];
    const float* g2   = (const float*)d_in[16];
    const float* be2  = (const float*)d_in[17];

    float* scratch = nullptr;
    cudaGetSymbolAddress((void**)&scratch, g_scratch);
    float* xb  = scratch + XBUF;
    float* qb  = scratch + QBUF;
    float* kb  = scratch + KBUF;
    float* vb  = scratch + VBUF;
    float* ab  = scratch + ABUF;
    float* tb  = scratch + TBUF;
    float* yb  = scratch + YBUF;
    float* fb  = scratch + FBUF;
    float* scb = scratch + SCBUF;

    posenc_kernel<<<(Nz * Dz) / 256, 256>>>(x, xb);

    dim3 gproj(Dz / 128, Nz / 128);   // (4, 64)
    dim3 gff1(FFz / 128, Nz / 128);   // (16, 64)

    for (int l = 0; l < Lz; l++) {
        const float* Wql = Wq + (size_t)l * Dz * Dz;
        const float* Wkl = Wk + (size_t)l * Dz * Dz;
        const float* Wvl = Wv + (size_t)l * Dz * Dz;
        const float* Wol = Wo + (size_t)l * Dz * Dz;
        const float* W1l = W1 + (size_t)l * Dz * FFz;
        const float* W2l = W2 + (size_t)l * FFz * Dz;
        const float* bql = bq + (size_t)l * Dz;
        const float* bkl = bk + (size_t)l * Dz;
        const float* bvl = bv + (size_t)l * Dz;
        const float* bol = bo + (size_t)l * Dz;
        const float* b1l = b1 + (size_t)l * FFz;
        const float* b2l = b2 + (size_t)l * Dz;
        const float* g1l = g1 + (size_t)l * Dz;
        const float* be1l= be1+ (size_t)l * Dz;
        const float* g2l = g2 + (size_t)l * Dz;
        const float* be2l= be2+ (size_t)l * Dz;

        gemm_bias_kernel<false><<<gproj, 256>>>(xb, Wql, bql, qb, Dz, Dz);
        gemm_bias_kernel<false><<<gproj, 256>>>(xb, Wkl, bkl, kb, Dz, Dz);
        gemm_bias_kernel<false><<<gproj, 256>>>(xb, Wvl, bvl, vb, Dz, Dz);

        qk_kernel<<<dim3(Sz / 128, Sz / 128, Bz * Hz), 256>>>(qb, kb, scb);
        softmax_kernel<<<Bz * Hz * Sz, 256>>>(scb, lens);
        pv_kernel<<<dim3(Sz / 128, Bz * Hz), 128>>>(scb, vb, ab);

        gemm_bias_kernel<false><<<gproj, 256>>>(ab, Wol, bol, tb, Dz, Dz);
        ln_kernel<<<Nz, 256>>>(xb, tb, g1l, be1l, yb);

        gemm_bias_kernel<true><<<gff1, 256>>>(yb, W1l, b1l, fb, Dz, FFz);
        gemm_bias_kernel<false><<<gproj, 256>>>(fb, W2l, b2l, tb, FFz, Dz);

        float* dst = (l == Lz - 1) ? (float*)d_out : xb;
        ln_kernel<<<Nz, 256>>>(yb, tb, g2l, be2l, dst);
    }
}